// round 16
// baseline (speedup 1.0000x reference)
#include <cuda_runtime.h>
#include <math.h>
#include <stdint.h>

#define BB 4
#define NN 8192
#define KK 20
#define NK (NN*KK)
#define KN ((size_t)KK*NN)
#define NB2 2048

typedef unsigned long long ull;

// ------------- scratch (device globals; no allocation allowed) -------------
__device__ float4   g_p4[BB*NN];                  // original order (x,y,z,|p|^2)
__device__ float4   g_sp4[BB*NN];                 // sorted by x
__device__ int      g_sidx[BB*NN];                // sorted -> original index
__device__ float    g_sx[BB*NN];                  // sorted x (boundary checks)
__device__ unsigned g_key[BB*NN];                 // sort keys (fenc(x))
__device__ int      g_id[BB*NN];                  // sort payload
__device__ float    g_x[BB*6*NK];                 // [b][c][k][n_sorted]
__device__ float    g_mu[BB*6];
__device__ float    g_M[BB*21];
__device__ float    g_sum2[BB*8], g_sq2[BB*8];
__device__ unsigned g_max2[BB*64*KK], g_min2[BB*64*KK];
__device__ float    g_y3[BB*512*KK];
__device__ float    g_s3[BB*8], g_q3[BB*8];
__device__ float    g_y4[BB*1024*KK];
__device__ float    g_s4[BB*8], g_q4[BB*8];

__device__ __forceinline__ unsigned fenc(float f){
    unsigned u = __float_as_uint(f);
    return (u & 0x80000000u) ? ~u : (u | 0x80000000u);
}
__device__ __forceinline__ float fdec(unsigned u){
    u = (u & 0x80000000u) ? (u & 0x7FFFFFFFu) : ~u;
    return __uint_as_float(u);
}
__device__ __forceinline__ float elu1(float v){
    return v > 0.f ? v : expm1f(v);
}
__device__ __forceinline__ float eluf(float v){
    return v > 0.f ? v : (__expf(v) - 1.f);
}

#define FMA2(d,a,b,c) asm("fma.rn.f32x2 %0, %1, %2, %3;" : "=l"(d) : "l"(a), "l"(b), "l"(c))
#define MUL2(d,a,b)   asm("mul.rn.f32x2 %0, %1, %2;"     : "=l"(d) : "l"(a), "l"(b))
__device__ __forceinline__ ull pk2(float lo, float hi){
    ull r; asm("mov.b64 %0, {%1,%2};" : "=l"(r) : "f"(lo), "f"(hi)); return r;
}
__device__ __forceinline__ void up2(ull v, float& lo, float& hi){
    asm("mov.b64 {%0,%1}, %2;" : "=f"(lo), "=f"(hi) : "l"(v));
}
__device__ __forceinline__ ull elu2f(ull v){
    float lo, hi; up2(v, lo, hi);
    return pk2(eluf(lo), eluf(hi));
}

// --------------------- init + pack (32768 threads) --------------------------
__global__ void k_initpack(const float* __restrict__ pts){
    int i = blockIdx.x*256 + threadIdx.x;
    if (i < BB*64*KK){ g_max2[i] = 0u; g_min2[i] = 0xFFFFFFFFu; }
    if (i < BB*6)  g_mu[i] = 0.f;
    if (i < BB*21) g_M[i]  = 0.f;
    if (i < BB*8){
        g_sum2[i]=0.f; g_sq2[i]=0.f;
        g_s3[i]=0.f; g_q3[i]=0.f; g_s4[i]=0.f; g_q4[i]=0.f;
    }
    int b = i >> 13, n = i & (NN-1);
    const float* P = pts + (size_t)b*3*NN;
    float x = P[n], y = P[NN+n], z = P[2*NN+n];
    g_p4[i] = make_float4(x, y, z, fmaf(z,z, fmaf(y,y, x*x)));
}

// ----------------- hierarchical bitonic sort by x ----------------------------
__global__ void __launch_bounds__(256) k_sortA(){
    int blk = blockIdx.x;
    int b = blk >> 2;
    int cb = (blk & 3) * NB2;
    __shared__ unsigned sk[NB2];
    __shared__ unsigned short si[NB2];
    int tid = threadIdx.x;
    for (int i = tid; i < NB2; i += 256){
        sk[i] = fenc(g_p4[b*NN + cb + i].x);
        si[i] = (unsigned short)(cb + i);
    }
    __syncthreads();
    for (int ksz = 2; ksz <= NB2; ksz <<= 1){
        for (int j = ksz >> 1; j > 0; j >>= 1){
            for (int t = tid; t < NB2/2; t += 256){
                int i = 2*t - (t & (j-1));
                int p = i + j;
                bool up = (((cb + i) & ksz) == 0);
                unsigned a = sk[i], c = sk[p];
                bool sw = up ? (a > c) : (a < c);
                if (sw){
                    sk[i] = c; sk[p] = a;
                    unsigned short tmp = si[i]; si[i] = si[p]; si[p] = tmp;
                }
            }
            __syncthreads();
        }
    }
    for (int i = tid; i < NB2; i += 256){
        g_key[b*NN + cb + i] = sk[i];
        g_id [b*NN + cb + i] = (int)si[i];
    }
}

__global__ void k_sortG(int ksz, int j){
    int t = blockIdx.x*256 + threadIdx.x;      // BB * NN/2 threads
    int b = t >> 12;
    int tt = t & 4095;
    int i = 2*tt - (tt & (j-1));
    int p = i + j;
    bool up = ((i & ksz) == 0);
    unsigned a = g_key[b*NN+i], c = g_key[b*NN+p];
    bool sw = up ? (a > c) : (a < c);
    if (sw){
        g_key[b*NN+i] = c; g_key[b*NN+p] = a;
        int ta = g_id[b*NN+i]; g_id[b*NN+i] = g_id[b*NN+p]; g_id[b*NN+p] = ta;
    }
}

__global__ void __launch_bounds__(256) k_sortB(int ksz, int fin){
    int blk = blockIdx.x;
    int b = blk >> 2;
    int cb = (blk & 3) * NB2;
    __shared__ unsigned sk[NB2];
    __shared__ unsigned short si[NB2];
    int tid = threadIdx.x;
    for (int i = tid; i < NB2; i += 256){
        sk[i] = g_key[b*NN + cb + i];
        si[i] = (unsigned short)g_id[b*NN + cb + i];
    }
    __syncthreads();
    for (int j = 1024; j > 0; j >>= 1){
        for (int t = tid; t < NB2/2; t += 256){
            int i = 2*t - (t & (j-1));
            int p = i + j;
            bool up = (((cb + i) & ksz) == 0);
            unsigned a = sk[i], c = sk[p];
            bool sw = up ? (a > c) : (a < c);
            if (sw){
                sk[i] = c; sk[p] = a;
                unsigned short tmp = si[i]; si[i] = si[p]; si[p] = tmp;
            }
        }
        __syncthreads();
    }
    if (fin){
        for (int i = tid; i < NB2; i += 256){
            int oi = (int)si[i];
            float4 pv = g_p4[b*NN + oi];
            g_sp4 [b*NN + cb + i] = pv;
            g_sidx[b*NN + cb + i] = oi;
            g_sx  [b*NN + cb + i] = pv.x;
        }
    } else {
        for (int i = tid; i < NB2; i += 256){
            g_key[b*NN + cb + i] = sk[i];
            g_id [b*NN + cb + i] = (int)si[i];
        }
    }
}

// lexicographic insert: exact lax.top_k (dist, orig_idx) ordering, any arrival
__device__ __forceinline__ void ins_lex(float ddv, int jv,
        float& df, int& ji, float& th, int& j19, int lane){
    unsigned pre = __ballot_sync(0xFFFFFFFFu,
        (df < ddv) || (df == ddv && ji < jv));
    int p = __popc(pre & 0xFFFFFu);
    float dup = __shfl_up_sync(0xFFFFFFFFu, df, 1);
    int   iup = __shfl_up_sync(0xFFFFFFFFu, ji, 1);
    if (lane > p){ df = dup; ji = iup; }
    else if (lane == p){ df = ddv; ji = jv; }
    th  = __shfl_sync(0xFFFFFFFFu, df, 19);
    j19 = __shfl_sync(0xFFFFFFFFu, ji, 19);
}

__device__ __forceinline__ void knn_batch(int boff, int B, int lane,
        float4 qa, float4 qb,
        float& df0, int& ji0, float& th0, int& j19_0,
        float& df1, int& ji1, float& th1, int& j19_1){
    int addr = boff + B*32 + lane;
    float4 c = g_sp4[addr];
    int cidx = g_sidx[addr];
    float dd0 = fmaf(-2.f, fmaf(qa.z,c.z, fmaf(qa.y,c.y, qa.x*c.x)), qa.w + c.w);
    float dd1 = fmaf(-2.f, fmaf(qb.z,c.z, fmaf(qb.y,c.y, qb.x*c.x)), qb.w + c.w);
    bool a0 = (dd0 < th0) || (dd0 == th0 && cidx < j19_0);
    bool a1 = (dd1 < th1) || (dd1 == th1 && cidx < j19_1);
    unsigned bal = __ballot_sync(0xFFFFFFFFu, a0 || a1);
    while (bal){
        int s = __ffs(bal) - 1; bal &= bal - 1;
        float d0v = __shfl_sync(0xFFFFFFFFu, dd0, s);
        float d1v = __shfl_sync(0xFFFFFFFFu, dd1, s);
        int   civ = __shfl_sync(0xFFFFFFFFu, cidx, s);
        if (d0v < th0 || (d0v == th0 && civ < j19_0))
            ins_lex(d0v, civ, df0, ji0, th0, j19_0, lane);
        if (d1v < th1 || (d1v == th1 && civ < j19_1))
            ins_lex(d1v, civ, df1, ji1, th1, j19_1, lane);
    }
}

// ---- KNN: sorted-window scan, 2 queries/warp, exact lexicographic top-20 ---
__global__ void __launch_bounds__(256) k_knn(){
    int b = blockIdx.y;
    int tid = threadIdx.x;
    int lane = tid & 31;
    int w = tid >> 5;
    int nb = blockIdx.x*16;                 // sorted positions
    int boff = b*NN;

    __shared__ float sx[120*17];
    __shared__ float sAcc[27];
    if (tid < 27) sAcc[tid] = 0.f;
    __syncthreads();

    int s0 = nb + w*2;
    float4 qa = g_sp4[boff + s0];
    float4 qb = g_sp4[boff + s0 + 1];

    float df0 = INFINITY, df1 = INFINITY;
    float th0 = INFINITY, th1 = INFINITY;
    int   ji0 = 0x7FFFFFFF, ji1 = 0x7FFFFFFF;
    int   j19_0 = 0x7FFFFFFF, j19_1 = 0x7FFFFFFF;

    const int NBATCH = NN/32;
    int L = s0 >> 5, R = L;
    knn_batch(boff, L, lane, qa, qb, df0,ji0,th0,j19_0, df1,ji1,th1,j19_1);

    while (1){
        bool okR = false, okL = false;
        float cR = 3.0e38f, cL = 3.0e38f;
        if (R + 1 < NBATCH){
            float xr = g_sx[boff + (R+1)*32];
            float a = xr - qa.x, bq = xr - qb.x;
            okR = (a*a <= th0) || (bq*bq <= th1);
            cR = bq;                         // nearest-side delta (>= 0)
        }
        if (L > 0){
            float xl = g_sx[boff + L*32 - 1];
            float a = qa.x - xl, bq = qb.x - xl;
            okL = (a*a <= th0) || (bq*bq <= th1);
            cL = a;                          // nearest-side delta (>= 0)
        }
        if (okR && (!okL || cR <= cL)){
            R++; knn_batch(boff, R, lane, qa, qb, df0,ji0,th0,j19_0, df1,ji1,th1,j19_1);
        } else if (okL){
            L--; knn_batch(boff, L, lane, qa, qb, df0,ji0,th0,j19_0, df1,ji1,th1,j19_1);
        } else break;
    }

    // gather (original coords via orig index), stage x, accumulate moments
    float macc = 0.f;
    const float K20 = 20.f;
#pragma unroll
    for (int qi=0; qi<2; qi++){
        float qx = qi ? qb.x : qa.x;
        float qy = qi ? qb.y : qa.y;
        float qz = qi ? qb.z : qa.z;
        int   ji = qi ? ji1 : ji0;
        int col = w*2 + qi;
        float v3=0.f, v4=0.f, v5=0.f;
        if (lane < KK){
            float4 nbp = g_p4[boff + ji];
            v3 = nbp.x - qx; v4 = nbp.y - qy; v5 = nbp.z - qz;
            sx[(0*20+lane)*17+col] = qx;
            sx[(1*20+lane)*17+col] = qy;
            sx[(2*20+lane)*17+col] = qz;
            sx[(3*20+lane)*17+col] = v3;
            sx[(4*20+lane)*17+col] = v4;
            sx[(5*20+lane)*17+col] = v5;
        }
        float S0=v3, S1=v4, S2=v5;
        float P00=v3*v3, P01=v3*v4, P02=v3*v5, P11=v4*v4, P12=v4*v5, P22=v5*v5;
#pragma unroll
        for (int o=16;o>0;o>>=1){
            S0 += __shfl_xor_sync(0xFFFFFFFFu,S0,o);
            S1 += __shfl_xor_sync(0xFFFFFFFFu,S1,o);
            S2 += __shfl_xor_sync(0xFFFFFFFFu,S2,o);
            P00+= __shfl_xor_sync(0xFFFFFFFFu,P00,o);
            P01+= __shfl_xor_sync(0xFFFFFFFFu,P01,o);
            P02+= __shfl_xor_sync(0xFFFFFFFFu,P02,o);
            P11+= __shfl_xor_sync(0xFFFFFFFFu,P11,o);
            P12+= __shfl_xor_sync(0xFFFFFFFFu,P12,o);
            P22+= __shfl_xor_sync(0xFFFFFFFFu,P22,o);
        }
        float m[27];
        m[0]=K20*qx; m[1]=K20*qy; m[2]=K20*qz; m[3]=S0; m[4]=S1; m[5]=S2;
        m[6]=K20*qx*qx; m[7]=K20*qx*qy; m[8]=K20*qx*qz; m[9]=qx*S0; m[10]=qx*S1; m[11]=qx*S2;
        m[12]=K20*qy*qy; m[13]=K20*qy*qz; m[14]=qy*S0; m[15]=qy*S1; m[16]=qy*S2;
        m[17]=K20*qz*qz; m[18]=qz*S0; m[19]=qz*S1; m[20]=qz*S2;
        m[21]=P00; m[22]=P01; m[23]=P02;
        m[24]=P11; m[25]=P12;
        m[26]=P22;
        float mval = m[0];
#pragma unroll
        for (int i=1;i<27;i++) if (lane==i) mval = m[i];
        macc += mval;
    }
    if (lane < 27) atomicAdd(&sAcc[lane], macc);

    __syncthreads();
    if (tid < 27){
        if (tid < 6) atomicAdd(&g_mu[b*6+tid], sAcc[tid]);
        else         atomicAdd(&g_M[b*21+tid-6], sAcc[tid]);
    }
    for (int i=tid; i<120*16; i+=256){
        int row = i>>4, col = i&15;
        g_x[((size_t)b*120 + row)*NN + nb + col] = sx[row*17 + col];
    }
}

// ----- fused pass 2: 4 n/thread, gridDim.z ks split, REDUX stats -----------
__global__ void __launch_bounds__(320) k_pass2(const float* __restrict__ w0,
                                               const float* __restrict__ b0,
                                               const float* __restrict__ gm,
                                               const float* __restrict__ be,
                                               const float* __restrict__ w1,
                                               const float* __restrict__ b1){
    __shared__ ull  sW0d[192];
    __shared__ ull  sAd[32], sBd[32];
    __shared__ ull  sW1d[2048];
    __shared__ ull  sB1d[64];
    __shared__ unsigned sMx[640], sMn[640];
    __shared__ float sWS[10][8], sWQ[10][8];

    int b = blockIdx.y;
    int ks = blockIdx.z;
    int tid = threadIdx.x;
    int w = tid >> 5, lane = tid & 31;

    for (int i=tid;i<192;i+=320){ float t = w0[i]; sW0d[i] = pk2(t,t); }
    for (int i=tid;i<2048;i+=320){ float t = w1[i]; sW1d[i] = pk2(t,t); }
    for (int i=tid;i<64;i+=320){ float t = b1[i]; sB1d[i] = pk2(t,t); }
    if (lane < 8){ sWS[w][lane] = 0.f; sWQ[w][lane] = 0.f; }

    if (tid < 32){
        int c = tid;
        const float inv = 1.f/(float)NK;
        float muv[6], Mv[21];
#pragma unroll
        for (int i=0;i<6;i++)  muv[i] = g_mu[b*6+i]*inv;
#pragma unroll
        for (int i=0;i<21;i++) Mv[i]  = g_M[b*21+i]*inv;
        float wv[6];
#pragma unroll
        for (int i=0;i<6;i++) wv[i] = w0[c*6+i];
        float lin = 0.f;
#pragma unroll
        for (int i=0;i<6;i++) lin = fmaf(wv[i], muv[i], lin);
        float quad = 0.f; int mI = 0;
#pragma unroll
        for (int i=0;i<6;i++)
#pragma unroll
            for (int j=i;j<6;j++){
                float term = wv[i]*wv[j]*Mv[mI];
                quad += (i==j) ? term : 2.f*term;
                mI++;
            }
        float bb0 = b0[c];
        float Ey  = lin + bb0;
        float Ey2 = quad + 2.f*bb0*lin + bb0*bb0;
        float sE  = Ey  + __shfl_xor_sync(0xFFFFFFFFu, Ey,  1);
        float sE2 = Ey2 + __shfl_xor_sync(0xFFFFFFFFu, Ey2, 1);
        sE  += __shfl_xor_sync(0xFFFFFFFFu, sE,  2);
        sE2 += __shfl_xor_sync(0xFFFFFFFFu, sE2, 2);
        float mg = 0.25f*sE, e2 = 0.25f*sE2;
        float rs = rsqrtf(e2 - mg*mg + 1e-5f);
        float A  = gm[c]*rs;
        float Bc = fmaf(A, bb0, be[c] - mg*rs*gm[c]);
        sAd[c] = pk2(A,A); sBd[c] = pk2(Bc,Bc);
    }
    __syncthreads();

    int n0 = blockIdx.x*128 + lane*4;
    int kk = w + ks*10;
    float gsum = 0.f, gsq = 0.f;

    size_t base = ((size_t)(b*6)*KK + kk)*NN + n0;
    ull xpa[6], xpb[6];
#pragma unroll
    for (int c6=0;c6<6;c6++){
        float4 t = *(const float4*)&g_x[base + (size_t)c6*KN];
        xpa[c6] = pk2(t.x, t.y);
        xpb[c6] = pk2(t.z, t.w);
    }
    ull z2a[32], z2b[32];
#pragma unroll
    for (int zc=0;zc<32;zc++){
        ull acc, bcc;
        MUL2(acc, sW0d[zc*6], xpa[0]);
        MUL2(bcc, sW0d[zc*6], xpb[0]);
        FMA2(acc, sW0d[zc*6+1], xpa[1], acc);
        FMA2(bcc, sW0d[zc*6+1], xpb[1], bcc);
        FMA2(acc, sW0d[zc*6+2], xpa[2], acc);
        FMA2(bcc, sW0d[zc*6+2], xpb[2], bcc);
        FMA2(acc, sW0d[zc*6+3], xpa[3], acc);
        FMA2(bcc, sW0d[zc*6+3], xpb[3], bcc);
        FMA2(acc, sW0d[zc*6+4], xpa[4], acc);
        FMA2(bcc, sW0d[zc*6+4], xpb[4], bcc);
        FMA2(acc, sW0d[zc*6+5], xpa[5], acc);
        FMA2(bcc, sW0d[zc*6+5], xpb[5], bcc);
        FMA2(acc, sAd[zc], acc, sBd[zc]);
        FMA2(bcc, sAd[zc], bcc, sBd[zc]);
        z2a[zc] = elu2f(acc);
        z2b[zc] = elu2f(bcc);
    }

#pragma unroll 1
    for (int ch=0; ch<16; ch++){
        ull a0 = sB1d[ch*4+0], a1 = sB1d[ch*4+1], a2 = sB1d[ch*4+2], a3 = sB1d[ch*4+3];
        ull e0 = a0, e1 = a1, e2 = a2, e3 = a3;
        const ulonglong2* wp0 = (const ulonglong2*)(sW1d + (ch*4+0)*32);
        const ulonglong2* wp1 = (const ulonglong2*)(sW1d + (ch*4+1)*32);
        const ulonglong2* wp2 = (const ulonglong2*)(sW1d + (ch*4+2)*32);
        const ulonglong2* wp3 = (const ulonglong2*)(sW1d + (ch*4+3)*32);
#pragma unroll
        for (int j4=0;j4<8;j4++){
            ull za0 = z2a[j4*4+0], za1 = z2a[j4*4+1], za2 = z2a[j4*4+2], za3 = z2a[j4*4+3];
            ull zb0 = z2b[j4*4+0], zb1 = z2b[j4*4+1], zb2 = z2b[j4*4+2], zb3 = z2b[j4*4+3];
            ulonglong2 wa0 = wp0[j4*2], wb0 = wp0[j4*2+1];
            FMA2(a0, wa0.x, za0, a0); FMA2(e0, wa0.x, zb0, e0);
            FMA2(a0, wa0.y, za1, a0); FMA2(e0, wa0.y, zb1, e0);
            FMA2(a0, wb0.x, za2, a0); FMA2(e0, wb0.x, zb2, e0);
            FMA2(a0, wb0.y, za3, a0); FMA2(e0, wb0.y, zb3, e0);
            ulonglong2 wa1 = wp1[j4*2], wb1 = wp1[j4*2+1];
            FMA2(a1, wa1.x, za0, a1); FMA2(e1, wa1.x, zb0, e1);
            FMA2(a1, wa1.y, za1, a1); FMA2(e1, wa1.y, zb1, e1);
            FMA2(a1, wb1.x, za2, a1); FMA2(e1, wb1.x, zb2, e1);
            FMA2(a1, wb1.y, za3, a1); FMA2(e1, wb1.y, zb3, e1);
            ulonglong2 wa2 = wp2[j4*2], wb2 = wp2[j4*2+1];
            FMA2(a2, wa2.x, za0, a2); FMA2(e2, wa2.x, zb0, e2);
            FMA2(a2, wa2.y, za1, a2); FMA2(e2, wa2.y, zb1, e2);
            FMA2(a2, wb2.x, za2, a2); FMA2(e2, wb2.x, zb2, e2);
            FMA2(a2, wb2.y, za3, a2); FMA2(e2, wb2.y, zb3, e2);
            ulonglong2 wa3 = wp3[j4*2], wb3 = wp3[j4*2+1];
            FMA2(a3, wa3.x, za0, a3); FMA2(e3, wa3.x, zb0, e3);
            FMA2(a3, wa3.y, za1, a3); FMA2(e3, wa3.y, zb1, e3);
            FMA2(a3, wb3.x, za2, a3); FMA2(e3, wb3.x, zb2, e3);
            FMA2(a3, wb3.y, za3, a3); FMA2(e3, wb3.y, zb3, e3);
        }
        float l0,h0,l1,h1,l2,h2,l3,h3, p0,r0,p1,r1,p2,r2,p3,r3;
        up2(a0,l0,h0); up2(e0,p0,r0);
        up2(a1,l1,h1); up2(e1,p1,r1);
        up2(a2,l2,h2); up2(e2,p2,r2);
        up2(a3,l3,h3); up2(e3,p3,r3);
        float mx0=fmaxf(fmaxf(l0,h0),fmaxf(p0,r0)), mn0=fminf(fminf(l0,h0),fminf(p0,r0));
        float mx1=fmaxf(fmaxf(l1,h1),fmaxf(p1,r1)), mn1=fminf(fminf(l1,h1),fminf(p1,r1));
        float mx2=fmaxf(fmaxf(l2,h2),fmaxf(p2,r2)), mn2=fminf(fminf(l2,h2),fminf(p2,r2));
        float mx3=fmaxf(fmaxf(l3,h3),fmaxf(p3,r3)), mn3=fminf(fminf(l3,h3),fminf(p3,r3));
        gsum += (l0+h0)+(p0+r0) + (l1+h1)+(p1+r1) + (l2+h2)+(p2+r2) + (l3+h3)+(p3+r3);
        gsq = fmaf(l0,l0, fmaf(h0,h0, fmaf(p0,p0, fmaf(r0,r0, gsq))));
        gsq = fmaf(l1,l1, fmaf(h1,h1, fmaf(p1,p1, fmaf(r1,r1, gsq))));
        gsq = fmaf(l2,l2, fmaf(h2,h2, fmaf(p2,p2, fmaf(r2,r2, gsq))));
        gsq = fmaf(l3,l3, fmaf(h3,h3, fmaf(p3,p3, fmaf(r3,r3, gsq))));
        unsigned rx0 = __reduce_max_sync(0xFFFFFFFFu, fenc(mx0));
        unsigned rn0 = __reduce_min_sync(0xFFFFFFFFu, fenc(mn0));
        unsigned rx1 = __reduce_max_sync(0xFFFFFFFFu, fenc(mx1));
        unsigned rn1 = __reduce_min_sync(0xFFFFFFFFu, fenc(mn1));
        unsigned rx2 = __reduce_max_sync(0xFFFFFFFFu, fenc(mx2));
        unsigned rn2 = __reduce_min_sync(0xFFFFFFFFu, fenc(mn2));
        unsigned rx3 = __reduce_max_sync(0xFFFFFFFFu, fenc(mx3));
        unsigned rn3 = __reduce_min_sync(0xFFFFFFFFu, fenc(mn3));
        if (lane == 0){
            sMx[(ch*4+0)*10+w] = rx0; sMn[(ch*4+0)*10+w] = rn0;
            sMx[(ch*4+1)*10+w] = rx1; sMn[(ch*4+1)*10+w] = rn1;
            sMx[(ch*4+2)*10+w] = rx2; sMn[(ch*4+2)*10+w] = rn2;
            sMx[(ch*4+3)*10+w] = rx3; sMn[(ch*4+3)*10+w] = rn3;
        }
        if (ch & 1){
            float fs = gsum, fq = gsq;
#pragma unroll
            for (int o=16;o>0;o>>=1){
                fs += __shfl_xor_sync(0xFFFFFFFFu, fs, o);
                fq += __shfl_xor_sync(0xFFFFFFFFu, fq, o);
            }
            if (lane == 0){
                sWS[w][ch>>1] += fs;
                sWQ[w][ch>>1] += fq;
            }
            gsum = 0.f; gsq = 0.f;
        }
    }
    __syncthreads();

    for (int i=tid;i<640;i+=320){
        int c = i/10, wl = i - (i/10)*10;
        int gi = (b*64 + c)*KK + wl + ks*10;
        atomicMax(&g_max2[gi], sMx[i]);
        atomicMin(&g_min2[gi], sMn[i]);
    }
    if (tid < 8){
        float s=0.f, q=0.f;
#pragma unroll
        for (int w2=0;w2<10;w2++){ s += sWS[w2][tid]; q += sWQ[w2][tid]; }
        atomicAdd(&g_sum2[b*8+tid], s);
        atomicAdd(&g_sq2[b*8+tid],  q);
    }
}

// ------ tail 1: GN2 on max/min -> ELU -> y3 (64->512); grid (KK, BB) -------
__global__ void __launch_bounds__(512) k_tail1(const float* __restrict__ g2,
                                               const float* __restrict__ be2,
                                               const float* __restrict__ w2,
                                               const float* __restrict__ b2){
    int b = blockIdx.y, kq = blockIdx.x;
    int tid = threadIdx.x;
    __shared__ float sx3[64];

    if (tid < 64){
        int c = tid, g = c>>3;
        float cnt = 8.f*(float)NK;
        float m = g_sum2[b*8+g]/cnt;
        float v = g_sq2[b*8+g]/cnt - m*m;
        float rs = rsqrtf(v + 1e-5f);
        float A = g2[c]*rs, Bc = be2[c] - m*A;
        float fmx = fdec(g_max2[(b*64+c)*KK+kq]);
        float fmn = fdec(g_min2[(b*64+c)*KK+kq]);
        float val = (A >= 0.f) ? fmx : fmn;
        sx3[c] = elu1(fmaf(A, val, Bc));
    }
    __syncthreads();

    int c4 = tid;
    float acc = b2[c4];
    const float4* wv = (const float4*)&w2[c4*64];
#pragma unroll
    for (int j=0;j<16;j++){
        float4 q = wv[j];
        acc = fmaf(q.x, sx3[j*4+0], acc);
        acc = fmaf(q.y, sx3[j*4+1], acc);
        acc = fmaf(q.z, sx3[j*4+2], acc);
        acc = fmaf(q.w, sx3[j*4+3], acc);
    }
    g_y3[((size_t)b*512 + c4)*KK + kq] = acc;

    float sm = acc, sq = acc*acc;
#pragma unroll
    for (int o=16;o>0;o>>=1){
        sm += __shfl_xor_sync(0xFFFFFFFFu, sm, o);
        sq += __shfl_xor_sync(0xFFFFFFFFu, sq, o);
    }
    if ((tid&31)==0){
        atomicAdd(&g_s3[b*8 + (c4>>6)], sm);
        atomicAdd(&g_q3[b*8 + (c4>>6)], sq);
    }
}

// ------ tail 2: z3 = ELU(GN3(y3)) smem-cached; y4 (512->1024) + GN4 stats ---
__global__ void __launch_bounds__(256) k_tail2(const float* __restrict__ g3c,
                                               const float* __restrict__ be3,
                                               const float* __restrict__ w3,
                                               const float* __restrict__ b3){
    __shared__ float sz[512*KK];
    __shared__ float sm3[8], sr3[8];
    __shared__ float s4[8], q4[8];

    int blk = blockIdx.x;
    int b = blk/80;
    int tid = threadIdx.x;

    if (tid < 8){
        float cnt = 64.f*(float)KK;
        float m = g_s3[b*8+tid]/cnt;
        float v = g_q3[b*8+tid]/cnt - m*m;
        sm3[tid] = m; sr3[tid] = rsqrtf(v + 1e-5f);
        s4[tid] = 0.f; q4[tid] = 0.f;
    }
    __syncthreads();

    for (int i=tid; i<512*KK; i+=256){
        int c = i/KK;
        int g = c>>6;
        float y = g_y3[(size_t)b*512*KK + i];
        float A = g3c[c]*sr3[g];
        sz[i] = elu1(fmaf(A, y, be3[c] - sm3[g]*A));
    }
    __syncthreads();

    int o = blk*256 + tid;
    int r = o - b*1024*KK;
    int c4 = r/KK, k = r%KK;
    float acc = b3[c4];
    const float* w = &w3[(size_t)c4*512];
#pragma unroll 8
    for (int j=0;j<512;j++) acc = fmaf(w[j], sz[j*KK+k], acc);
    g_y4[o] = acc;
    atomicAdd(&s4[c4>>7], acc);
    atomicAdd(&q4[c4>>7], acc*acc);
    __syncthreads();
    if (tid < 8){
        atomicAdd(&g_s4[b*8+tid], s4[tid]);
        atomicAdd(&g_q4[b*8+tid], q4[tid]);
    }
}

// ----------------------------- finalize -------------------------------------
__global__ void k_fin(const float* __restrict__ g4, const float* __restrict__ be4,
                      float* __restrict__ out){
    int o = blockIdx.x*256 + threadIdx.x;
    if (o >= BB*1024*KK) return;
    int b = o/(1024*KK);
    int r = o - b*1024*KK;
    int c = r/KK;
    int g = c>>7;
    float cnt = 128.f*(float)KK;
    float m = g_s4[b*8+g]/cnt;
    float v = g_q4[b*8+g]/cnt - m*m;
    float rs = rsqrtf(v + 1e-5f);
    float A = g4[c]*rs;
    out[o] = elu1(fmaf(A, g_y4[o], be4[c] - m*A));
}

// -----------------------------------------------------------------------------
extern "C" void kernel_launch(void* const* d_in, const int* in_sizes, int n_in,
                              void* d_out, int out_size){
    const float* pts  = (const float*)d_in[0];
    const float* p1w0 = (const float*)d_in[1];
    const float* p1b0 = (const float*)d_in[2];
    const float* p1g0 = (const float*)d_in[3];
    const float* p1be0= (const float*)d_in[4];
    const float* p1w1 = (const float*)d_in[5];
    const float* p1b1 = (const float*)d_in[6];
    const float* p1g1 = (const float*)d_in[7];
    const float* p1be1= (const float*)d_in[8];
    const float* p2w0 = (const float*)d_in[9];
    const float* p2b0 = (const float*)d_in[10];
    const float* p2g0 = (const float*)d_in[11];
    const float* p2be0= (const float*)d_in[12];
    const float* p2w1 = (const float*)d_in[13];
    const float* p2b1 = (const float*)d_in[14];
    const float* p2g1 = (const float*)d_in[15];
    const float* p2be1= (const float*)d_in[16];
    float* out = (float*)d_out;

    k_initpack<<<128, 256>>>(pts);
    k_sortA<<<BB*4, 256>>>();
    k_sortG<<<BB*NN/2/256, 256>>>(4096, 2048);
    k_sortB<<<BB*4, 256>>>(4096, 0);
    k_sortG<<<BB*NN/2/256, 256>>>(8192, 4096);
    k_sortG<<<BB*NN/2/256, 256>>>(8192, 2048);
    k_sortB<<<BB*4, 256>>>(8192, 1);
    k_knn<<<dim3(NN/16, BB), 256>>>();
    k_pass2<<<dim3(NN/128, BB, 2), 320>>>(p1w0, p1b0, p1g0, p1be0, p1w1, p1b1);
    k_tail1<<<dim3(KK, BB), 512>>>(p1g1, p1be1, p2w0, p2b0);
    k_tail2<<<BB*80, 256>>>(p2g0, p2be0, p2w1, p2b1);
    k_fin<<<(BB*1024*KK + 255)/256, 256>>>(p2g1, p2be1, out);
}

// round 17
// speedup vs baseline: 1.4097x; 1.4097x over previous
#include <cuda_runtime.h>
#include <math.h>
#include <stdint.h>

#define BB 4
#define NN 8192
#define KK 20
#define NK (NN*KK)
#define KN ((size_t)KK*NN)

typedef unsigned long long ull;

// ------------- scratch (device globals; no allocation allowed) -------------
__device__ float4   g_p4[BB*NN];
__device__ float    g_x[BB*6*NK];                 // [b][c][k][n]
__device__ float    g_mu[BB*6];
__device__ float    g_M[BB*21];
__device__ float    g_sum2[BB*8], g_sq2[BB*8];
__device__ unsigned g_max2[BB*64*KK], g_min2[BB*64*KK];
__device__ float    g_y3[BB*512*KK];
__device__ float    g_s3[BB*8], g_q3[BB*8];
__device__ float    g_y4[BB*1024*KK];
__device__ float    g_s4[BB*8], g_q4[BB*8];

__device__ __forceinline__ unsigned fenc(float f){
    unsigned u = __float_as_uint(f);
    return (u & 0x80000000u) ? ~u : (u | 0x80000000u);
}
__device__ __forceinline__ float fdec(unsigned u){
    u = (u & 0x80000000u) ? (u & 0x7FFFFFFFu) : ~u;
    return __uint_as_float(u);
}
__device__ __forceinline__ float elu1(float v){
    return v > 0.f ? v : expm1f(v);
}
__device__ __forceinline__ float eluf(float v){
    return v > 0.f ? v : (__expf(v) - 1.f);
}

#define FMA2(d,a,b,c) asm("fma.rn.f32x2 %0, %1, %2, %3;" : "=l"(d) : "l"(a), "l"(b), "l"(c))
#define MUL2(d,a,b)   asm("mul.rn.f32x2 %0, %1, %2;"     : "=l"(d) : "l"(a), "l"(b))
__device__ __forceinline__ ull pk2(float lo, float hi){
    ull r; asm("mov.b64 %0, {%1,%2};" : "=l"(r) : "f"(lo), "f"(hi)); return r;
}
__device__ __forceinline__ void up2(ull v, float& lo, float& hi){
    asm("mov.b64 {%0,%1}, %2;" : "=f"(lo), "=f"(hi) : "l"(v));
}
__device__ __forceinline__ ull elu2f(ull v){
    float lo, hi; up2(v, lo, hi);
    return pk2(eluf(lo), eluf(hi));
}

// --------------------- init + pack fused (32768 threads) -------------------
__global__ void k_initpack(const float* __restrict__ pts){
    int i = blockIdx.x*256 + threadIdx.x;
    if (i < BB*64*KK){ g_max2[i] = 0u; g_min2[i] = 0xFFFFFFFFu; }
    if (i < BB*6)  g_mu[i] = 0.f;
    if (i < BB*21) g_M[i]  = 0.f;
    if (i < BB*8){
        g_sum2[i]=0.f; g_sq2[i]=0.f;
        g_s3[i]=0.f; g_q3[i]=0.f; g_s4[i]=0.f; g_q4[i]=0.f;
    }
    int b = i >> 13, n = i & (NN-1);
    const float* P = pts + (size_t)b*3*NN;
    float x = P[n], y = P[NN+n], z = P[2*NN+n];
    g_p4[i] = make_float4(x, y, z, fmaf(z,z, fmaf(y,y, x*x)));
}

// insert one candidate (warp-uniform ddv) into the distributed sorted list
__device__ __forceinline__ void ins_dist(float ddv, int jv,
                                         float& df, int& ji, float& th, int lane){
    int p = __popc(__ballot_sync(0xFFFFFFFFu, df <= ddv) & 0xFFFFFu);
    float dup = __shfl_up_sync(0xFFFFFFFFu, df, 1);
    int   iup = __shfl_up_sync(0xFFFFFFFFu, ji, 1);
    if (lane > p){ df = dup; ji = iup; }
    else if (lane == p){ df = ddv; ji = jv; }
    th = __shfl_sync(0xFFFFFFFFu, df, 19);
}

// combined drain: one ballot batch covers both queries; re-filter inside
__device__ __forceinline__ void drain2q(unsigned bal, float dd0, float dd1, int jbase,
                                        float& df0, int& ji0, float& th0,
                                        float& df1, int& ji1, float& th1, int lane){
    while (bal){
        int s = __ffs(bal) - 1; bal &= bal - 1;
        float d0v = __shfl_sync(0xFFFFFFFFu, dd0, s);
        float d1v = __shfl_sync(0xFFFFFFFFu, dd1, s);
        int jv = jbase + s;
        if (d0v < th0) ins_dist(d0v, jv, df0, ji0, th0, lane);
        if (d1v < th1) ins_dist(d1v, jv, df1, ji1, th1, lane);
    }
}

// ------ KNN: 2 queries/warp, combined-query ballots, distributed top-20 ----
__global__ void __launch_bounds__(256) k_knn(){
    int b = blockIdx.y;
    int tid = threadIdx.x;
    int lane = tid & 31;
    int w = tid >> 5;
    int nb = blockIdx.x*16;
    const float4* __restrict__ P4 = g_p4 + b*NN;

    __shared__ float sx[120*17];
    __shared__ float sAcc[27];
    if (tid < 27) sAcc[tid] = 0.f;
    __syncthreads();

    float4 qa = P4[nb + w*2 + 0];
    float4 qb = P4[nb + w*2 + 1];
    float q0x=qa.x, q0y=qa.y, q0z=qa.z, q0s=qa.w;
    float q1x=qb.x, q1y=qb.y, q1z=qb.z, q1s=qb.w;

    float df0 = INFINITY, df1 = INFINITY;
    float th0 = INFINITY, th1 = INFINITY;
    int   ji0 = 0x7FFFFFFF, ji1 = 0x7FFFFFFF;

#pragma unroll 4
    for (int t=0; t<NN/64; t++){
        float4 c0 = P4[t*64 + lane];
        float4 c1 = P4[t*64 + 32 + lane];
        float dot00 = fmaf(q0z,c0.z, fmaf(q0y,c0.y, q0x*c0.x));
        float dot01 = fmaf(q0z,c1.z, fmaf(q0y,c1.y, q0x*c1.x));
        float dot10 = fmaf(q1z,c0.z, fmaf(q1y,c0.y, q1x*c0.x));
        float dot11 = fmaf(q1z,c1.z, fmaf(q1y,c1.y, q1x*c1.x));
        float dd00 = fmaf(-2.f, dot00, q0s + c0.w);
        float dd01 = fmaf(-2.f, dot01, q0s + c1.w);
        float dd10 = fmaf(-2.f, dot10, q1s + c0.w);
        float dd11 = fmaf(-2.f, dot11, q1s + c1.w);
        unsigned b0 = __ballot_sync(0xFFFFFFFFu, (dd00 < th0) || (dd10 < th1));
        unsigned b1 = __ballot_sync(0xFFFFFFFFu, (dd01 < th0) || (dd11 < th1));
        drain2q(b0, dd00, dd10, t*64,      df0, ji0, th0, df1, ji1, th1, lane);
        drain2q(b1, dd01, dd11, t*64 + 32, df0, ji0, th0, df1, ji1, th1, lane);
    }

    float macc = 0.f;
    const float K20 = 20.f;
#pragma unroll
    for (int qi=0; qi<2; qi++){
        float qx = qi ? q1x : q0x;
        float qy = qi ? q1y : q0y;
        float qz = qi ? q1z : q0z;
        int   ji = qi ? ji1 : ji0;
        int col = w*2 + qi;
        float v3=0.f, v4=0.f, v5=0.f;
        if (lane < KK){
            float4 nbp = P4[ji];
            v3 = nbp.x - qx; v4 = nbp.y - qy; v5 = nbp.z - qz;
            sx[(0*20+lane)*17+col] = qx;
            sx[(1*20+lane)*17+col] = qy;
            sx[(2*20+lane)*17+col] = qz;
            sx[(3*20+lane)*17+col] = v3;
            sx[(4*20+lane)*17+col] = v4;
            sx[(5*20+lane)*17+col] = v5;
        }
        float S0=v3, S1=v4, S2=v5;
        float P00=v3*v3, P01=v3*v4, P02=v3*v5, P11=v4*v4, P12=v4*v5, P22=v5*v5;
#pragma unroll
        for (int o=16;o>0;o>>=1){
            S0 += __shfl_xor_sync(0xFFFFFFFFu,S0,o);
            S1 += __shfl_xor_sync(0xFFFFFFFFu,S1,o);
            S2 += __shfl_xor_sync(0xFFFFFFFFu,S2,o);
            P00+= __shfl_xor_sync(0xFFFFFFFFu,P00,o);
            P01+= __shfl_xor_sync(0xFFFFFFFFu,P01,o);
            P02+= __shfl_xor_sync(0xFFFFFFFFu,P02,o);
            P11+= __shfl_xor_sync(0xFFFFFFFFu,P11,o);
            P12+= __shfl_xor_sync(0xFFFFFFFFu,P12,o);
            P22+= __shfl_xor_sync(0xFFFFFFFFu,P22,o);
        }
        float m[27];
        m[0]=K20*qx; m[1]=K20*qy; m[2]=K20*qz; m[3]=S0; m[4]=S1; m[5]=S2;
        m[6]=K20*qx*qx; m[7]=K20*qx*qy; m[8]=K20*qx*qz; m[9]=qx*S0; m[10]=qx*S1; m[11]=qx*S2;
        m[12]=K20*qy*qy; m[13]=K20*qy*qz; m[14]=qy*S0; m[15]=qy*S1; m[16]=qy*S2;
        m[17]=K20*qz*qz; m[18]=qz*S0; m[19]=qz*S1; m[20]=qz*S2;
        m[21]=P00; m[22]=P01; m[23]=P02;
        m[24]=P11; m[25]=P12;
        m[26]=P22;
        float mval = m[0];
#pragma unroll
        for (int i=1;i<27;i++) if (lane==i) mval = m[i];
        macc += mval;
    }
    if (lane < 27) atomicAdd(&sAcc[lane], macc);

    __syncthreads();
    if (tid < 27){
        if (tid < 6) atomicAdd(&g_mu[b*6+tid], sAcc[tid]);
        else         atomicAdd(&g_M[b*21+tid-6], sAcc[tid]);
    }
    for (int i=tid; i<120*16; i+=256){
        int row = i>>4, col = i&15;
        g_x[((size_t)b*120 + row)*NN + nb + col] = sx[row*17 + col];
    }
}

// ----- fused pass 2: 4 n/thread, gridDim.z ks split, REDUX stats -----------
__global__ void __launch_bounds__(320) k_pass2(const float* __restrict__ w0,
                                               const float* __restrict__ b0,
                                               const float* __restrict__ gm,
                                               const float* __restrict__ be,
                                               const float* __restrict__ w1,
                                               const float* __restrict__ b1){
    __shared__ ull  sW0d[192];
    __shared__ ull  sAd[32], sBd[32];
    __shared__ ull  sW1d[2048];
    __shared__ ull  sB1d[64];
    __shared__ unsigned sMx[640], sMn[640];
    __shared__ float sWS[10][8], sWQ[10][8];

    int b = blockIdx.y;
    int ks = blockIdx.z;
    int tid = threadIdx.x;
    int w = tid >> 5, lane = tid & 31;

    for (int i=tid;i<192;i+=320){ float t = w0[i]; sW0d[i] = pk2(t,t); }
    for (int i=tid;i<2048;i+=320){ float t = w1[i]; sW1d[i] = pk2(t,t); }
    for (int i=tid;i<64;i+=320){ float t = b1[i]; sB1d[i] = pk2(t,t); }
    if (lane < 8){ sWS[w][lane] = 0.f; sWQ[w][lane] = 0.f; }

    if (tid < 32){
        int c = tid;
        const float inv = 1.f/(float)NK;
        float muv[6], Mv[21];
#pragma unroll
        for (int i=0;i<6;i++)  muv[i] = g_mu[b*6+i]*inv;
#pragma unroll
        for (int i=0;i<21;i++) Mv[i]  = g_M[b*21+i]*inv;
        float wv[6];
#pragma unroll
        for (int i=0;i<6;i++) wv[i] = w0[c*6+i];
        float lin = 0.f;
#pragma unroll
        for (int i=0;i<6;i++) lin = fmaf(wv[i], muv[i], lin);
        float quad = 0.f; int mI = 0;
#pragma unroll
        for (int i=0;i<6;i++)
#pragma unroll
            for (int j=i;j<6;j++){
                float term = wv[i]*wv[j]*Mv[mI];
                quad += (i==j) ? term : 2.f*term;
                mI++;
            }
        float bb0 = b0[c];
        float Ey  = lin + bb0;
        float Ey2 = quad + 2.f*bb0*lin + bb0*bb0;
        float sE  = Ey  + __shfl_xor_sync(0xFFFFFFFFu, Ey,  1);
        float sE2 = Ey2 + __shfl_xor_sync(0xFFFFFFFFu, Ey2, 1);
        sE  += __shfl_xor_sync(0xFFFFFFFFu, sE,  2);
        sE2 += __shfl_xor_sync(0xFFFFFFFFu, sE2, 2);
        float mg = 0.25f*sE, e2 = 0.25f*sE2;
        float rs = rsqrtf(e2 - mg*mg + 1e-5f);
        float A  = gm[c]*rs;
        float Bc = fmaf(A, bb0, be[c] - mg*rs*gm[c]);
        sAd[c] = pk2(A,A); sBd[c] = pk2(Bc,Bc);
    }
    __syncthreads();

    int n0 = blockIdx.x*128 + lane*4;
    int kk = w + ks*10;
    float gsum = 0.f, gsq = 0.f;

    size_t base = ((size_t)(b*6)*KK + kk)*NN + n0;
    ull xpa[6], xpb[6];
#pragma unroll
    for (int c6=0;c6<6;c6++){
        float4 t = *(const float4*)&g_x[base + (size_t)c6*KN];
        xpa[c6] = pk2(t.x, t.y);
        xpb[c6] = pk2(t.z, t.w);
    }
    ull z2a[32], z2b[32];
#pragma unroll
    for (int zc=0;zc<32;zc++){
        ull acc, bcc;
        MUL2(acc, sW0d[zc*6], xpa[0]);
        MUL2(bcc, sW0d[zc*6], xpb[0]);
        FMA2(acc, sW0d[zc*6+1], xpa[1], acc);
        FMA2(bcc, sW0d[zc*6+1], xpb[1], bcc);
        FMA2(acc, sW0d[zc*6+2], xpa[2], acc);
        FMA2(bcc, sW0d[zc*6+2], xpb[2], bcc);
        FMA2(acc, sW0d[zc*6+3], xpa[3], acc);
        FMA2(bcc, sW0d[zc*6+3], xpb[3], bcc);
        FMA2(acc, sW0d[zc*6+4], xpa[4], acc);
        FMA2(bcc, sW0d[zc*6+4], xpb[4], bcc);
        FMA2(acc, sW0d[zc*6+5], xpa[5], acc);
        FMA2(bcc, sW0d[zc*6+5], xpb[5], bcc);
        FMA2(acc, sAd[zc], acc, sBd[zc]);
        FMA2(bcc, sAd[zc], bcc, sBd[zc]);
        z2a[zc] = elu2f(acc);
        z2b[zc] = elu2f(bcc);
    }

#pragma unroll 1
    for (int ch=0; ch<16; ch++){
        ull a0 = sB1d[ch*4+0], a1 = sB1d[ch*4+1], a2 = sB1d[ch*4+2], a3 = sB1d[ch*4+3];
        ull e0 = a0, e1 = a1, e2 = a2, e3 = a3;
        const ulonglong2* wp0 = (const ulonglong2*)(sW1d + (ch*4+0)*32);
        const ulonglong2* wp1 = (const ulonglong2*)(sW1d + (ch*4+1)*32);
        const ulonglong2* wp2 = (const ulonglong2*)(sW1d + (ch*4+2)*32);
        const ulonglong2* wp3 = (const ulonglong2*)(sW1d + (ch*4+3)*32);
#pragma unroll
        for (int j4=0;j4<8;j4++){
            ull za0 = z2a[j4*4+0], za1 = z2a[j4*4+1], za2 = z2a[j4*4+2], za3 = z2a[j4*4+3];
            ull zb0 = z2b[j4*4+0], zb1 = z2b[j4*4+1], zb2 = z2b[j4*4+2], zb3 = z2b[j4*4+3];
            ulonglong2 wa0 = wp0[j4*2], wb0 = wp0[j4*2+1];
            FMA2(a0, wa0.x, za0, a0); FMA2(e0, wa0.x, zb0, e0);
            FMA2(a0, wa0.y, za1, a0); FMA2(e0, wa0.y, zb1, e0);
            FMA2(a0, wb0.x, za2, a0); FMA2(e0, wb0.x, zb2, e0);
            FMA2(a0, wb0.y, za3, a0); FMA2(e0, wb0.y, zb3, e0);
            ulonglong2 wa1 = wp1[j4*2], wb1 = wp1[j4*2+1];
            FMA2(a1, wa1.x, za0, a1); FMA2(e1, wa1.x, zb0, e1);
            FMA2(a1, wa1.y, za1, a1); FMA2(e1, wa1.y, zb1, e1);
            FMA2(a1, wb1.x, za2, a1); FMA2(e1, wb1.x, zb2, e1);
            FMA2(a1, wb1.y, za3, a1); FMA2(e1, wb1.y, zb3, e1);
            ulonglong2 wa2 = wp2[j4*2], wb2 = wp2[j4*2+1];
            FMA2(a2, wa2.x, za0, a2); FMA2(e2, wa2.x, zb0, e2);
            FMA2(a2, wa2.y, za1, a2); FMA2(e2, wa2.y, zb1, e2);
            FMA2(a2, wb2.x, za2, a2); FMA2(e2, wb2.x, zb2, e2);
            FMA2(a2, wb2.y, za3, a2); FMA2(e2, wb2.y, zb3, e2);
            ulonglong2 wa3 = wp3[j4*2], wb3 = wp3[j4*2+1];
            FMA2(a3, wa3.x, za0, a3); FMA2(e3, wa3.x, zb0, e3);
            FMA2(a3, wa3.y, za1, a3); FMA2(e3, wa3.y, zb1, e3);
            FMA2(a3, wb3.x, za2, a3); FMA2(e3, wb3.x, zb2, e3);
            FMA2(a3, wb3.y, za3, a3); FMA2(e3, wb3.y, zb3, e3);
        }
        float l0,h0,l1,h1,l2,h2,l3,h3, p0,r0,p1,r1,p2,r2,p3,r3;
        up2(a0,l0,h0); up2(e0,p0,r0);
        up2(a1,l1,h1); up2(e1,p1,r1);
        up2(a2,l2,h2); up2(e2,p2,r2);
        up2(a3,l3,h3); up2(e3,p3,r3);
        float mx0=fmaxf(fmaxf(l0,h0),fmaxf(p0,r0)), mn0=fminf(fminf(l0,h0),fminf(p0,r0));
        float mx1=fmaxf(fmaxf(l1,h1),fmaxf(p1,r1)), mn1=fminf(fminf(l1,h1),fminf(p1,r1));
        float mx2=fmaxf(fmaxf(l2,h2),fmaxf(p2,r2)), mn2=fminf(fminf(l2,h2),fminf(p2,r2));
        float mx3=fmaxf(fmaxf(l3,h3),fmaxf(p3,r3)), mn3=fminf(fminf(l3,h3),fminf(p3,r3));
        gsum += (l0+h0)+(p0+r0) + (l1+h1)+(p1+r1) + (l2+h2)+(p2+r2) + (l3+h3)+(p3+r3);
        gsq = fmaf(l0,l0, fmaf(h0,h0, fmaf(p0,p0, fmaf(r0,r0, gsq))));
        gsq = fmaf(l1,l1, fmaf(h1,h1, fmaf(p1,p1, fmaf(r1,r1, gsq))));
        gsq = fmaf(l2,l2, fmaf(h2,h2, fmaf(p2,p2, fmaf(r2,r2, gsq))));
        gsq = fmaf(l3,l3, fmaf(h3,h3, fmaf(p3,p3, fmaf(r3,r3, gsq))));
        unsigned rx0 = __reduce_max_sync(0xFFFFFFFFu, fenc(mx0));
        unsigned rn0 = __reduce_min_sync(0xFFFFFFFFu, fenc(mn0));
        unsigned rx1 = __reduce_max_sync(0xFFFFFFFFu, fenc(mx1));
        unsigned rn1 = __reduce_min_sync(0xFFFFFFFFu, fenc(mn1));
        unsigned rx2 = __reduce_max_sync(0xFFFFFFFFu, fenc(mx2));
        unsigned rn2 = __reduce_min_sync(0xFFFFFFFFu, fenc(mn2));
        unsigned rx3 = __reduce_max_sync(0xFFFFFFFFu, fenc(mx3));
        unsigned rn3 = __reduce_min_sync(0xFFFFFFFFu, fenc(mn3));
        if (lane == 0){
            sMx[(ch*4+0)*10+w] = rx0; sMn[(ch*4+0)*10+w] = rn0;
            sMx[(ch*4+1)*10+w] = rx1; sMn[(ch*4+1)*10+w] = rn1;
            sMx[(ch*4+2)*10+w] = rx2; sMn[(ch*4+2)*10+w] = rn2;
            sMx[(ch*4+3)*10+w] = rx3; sMn[(ch*4+3)*10+w] = rn3;
        }
        if (ch & 1){
            float fs = gsum, fq = gsq;
#pragma unroll
            for (int o=16;o>0;o>>=1){
                fs += __shfl_xor_sync(0xFFFFFFFFu, fs, o);
                fq += __shfl_xor_sync(0xFFFFFFFFu, fq, o);
            }
            if (lane == 0){
                sWS[w][ch>>1] += fs;
                sWQ[w][ch>>1] += fq;
            }
            gsum = 0.f; gsq = 0.f;
        }
    }
    __syncthreads();

    for (int i=tid;i<640;i+=320){
        int c = i/10, wl = i - (i/10)*10;
        int gi = (b*64 + c)*KK + wl + ks*10;
        atomicMax(&g_max2[gi], sMx[i]);
        atomicMin(&g_min2[gi], sMn[i]);
    }
    if (tid < 8){
        float s=0.f, q=0.f;
#pragma unroll
        for (int w2=0;w2<10;w2++){ s += sWS[w2][tid]; q += sWQ[w2][tid]; }
        atomicAdd(&g_sum2[b*8+tid], s);
        atomicAdd(&g_sq2[b*8+tid],  q);
    }
}

// ------ tail 1: GN2 on max/min -> ELU -> y3 (64->512); grid (KK, BB) -------
__global__ void __launch_bounds__(512) k_tail1(const float* __restrict__ g2,
                                               const float* __restrict__ be2,
                                               const float* __restrict__ w2,
                                               const float* __restrict__ b2){
    int b = blockIdx.y, kq = blockIdx.x;
    int tid = threadIdx.x;
    __shared__ float sx3[64];

    if (tid < 64){
        int c = tid, g = c>>3;
        float cnt = 8.f*(float)NK;
        float m = g_sum2[b*8+g]/cnt;
        float v = g_sq2[b*8+g]/cnt - m*m;
        float rs = rsqrtf(v + 1e-5f);
        float A = g2[c]*rs, Bc = be2[c] - m*A;
        float fmx = fdec(g_max2[(b*64+c)*KK+kq]);
        float fmn = fdec(g_min2[(b*64+c)*KK+kq]);
        float val = (A >= 0.f) ? fmx : fmn;
        sx3[c] = elu1(fmaf(A, val, Bc));
    }
    __syncthreads();

    int c4 = tid;
    float acc = b2[c4];
    const float4* wv = (const float4*)&w2[c4*64];
#pragma unroll
    for (int j=0;j<16;j++){
        float4 q = wv[j];
        acc = fmaf(q.x, sx3[j*4+0], acc);
        acc = fmaf(q.y, sx3[j*4+1], acc);
        acc = fmaf(q.z, sx3[j*4+2], acc);
        acc = fmaf(q.w, sx3[j*4+3], acc);
    }
    g_y3[((size_t)b*512 + c4)*KK + kq] = acc;

    float sm = acc, sq = acc*acc;
#pragma unroll
    for (int o=16;o>0;o>>=1){
        sm += __shfl_xor_sync(0xFFFFFFFFu, sm, o);
        sq += __shfl_xor_sync(0xFFFFFFFFu, sq, o);
    }
    if ((tid&31)==0){
        atomicAdd(&g_s3[b*8 + (c4>>6)], sm);
        atomicAdd(&g_q3[b*8 + (c4>>6)], sq);
    }
}

// ------ tail 2: z3 = ELU(GN3(y3)) smem-cached; y4 (512->1024) + GN4 stats ---
__global__ void __launch_bounds__(256) k_tail2(const float* __restrict__ g3c,
                                               const float* __restrict__ be3,
                                               const float* __restrict__ w3,
                                               const float* __restrict__ b3){
    __shared__ float sz[512*KK];
    __shared__ float sm3[8], sr3[8];
    __shared__ float s4[8], q4[8];

    int blk = blockIdx.x;
    int b = blk/80;
    int tid = threadIdx.x;

    if (tid < 8){
        float cnt = 64.f*(float)KK;
        float m = g_s3[b*8+tid]/cnt;
        float v = g_q3[b*8+tid]/cnt - m*m;
        sm3[tid] = m; sr3[tid] = rsqrtf(v + 1e-5f);
        s4[tid] = 0.f; q4[tid] = 0.f;
    }
    __syncthreads();

    for (int i=tid; i<512*KK; i+=256){
        int c = i/KK;
        int g = c>>6;
        float y = g_y3[(size_t)b*512*KK + i];
        float A = g3c[c]*sr3[g];
        sz[i] = elu1(fmaf(A, y, be3[c] - sm3[g]*A));
    }
    __syncthreads();

    int o = blk*256 + tid;
    int r = o - b*1024*KK;
    int c4 = r/KK, k = r%KK;
    float acc = b3[c4];
    const float* w = &w3[(size_t)c4*512];
#pragma unroll 8
    for (int j=0;j<512;j++) acc = fmaf(w[j], sz[j*KK+k], acc);
    g_y4[o] = acc;
    atomicAdd(&s4[c4>>7], acc);
    atomicAdd(&q4[c4>>7], acc*acc);
    __syncthreads();
    if (tid < 8){
        atomicAdd(&g_s4[b*8+tid], s4[tid]);
        atomicAdd(&g_q4[b*8+tid], q4[tid]);
    }
}

// ----------------------------- finalize -------------------------------------
__global__ void k_fin(const float* __restrict__ g4, const float* __restrict__ be4,
                      float* __restrict__ out){
    int o = blockIdx.x*256 + threadIdx.x;
    if (o >= BB*1024*KK) return;
    int b = o/(1024*KK);
    int r = o - b*1024*KK;
    int c = r/KK;
    int g = c>>7;
    float cnt = 128.f*(float)KK;
    float m = g_s4[b*8+g]/cnt;
    float v = g_q4[b*8+g]/cnt - m*m;
    float rs = rsqrtf(v + 1e-5f);
    float A = g4[c]*rs;
    out[o] = elu1(fmaf(A, g_y4[o], be4[c] - m*A));
}

// -----------------------------------------------------------------------------
extern "C" void kernel_launch(void* const* d_in, const int* in_sizes, int n_in,
                              void* d_out, int out_size){
    const float* pts  = (const float*)d_in[0];
    const float* p1w0 = (const float*)d_in[1];
    const float* p1b0 = (const float*)d_in[2];
    const float* p1g0 = (const float*)d_in[3];
    const float* p1be0= (const float*)d_in[4];
    const float* p1w1 = (const float*)d_in[5];
    const float* p1b1 = (const float*)d_in[6];
    const float* p1g1 = (const float*)d_in[7];
    const float* p1be1= (const float*)d_in[8];
    const float* p2w0 = (const float*)d_in[9];
    const float* p2b0 = (const float*)d_in[10];
    const float* p2g0 = (const float*)d_in[11];
    const float* p2be0= (const float*)d_in[12];
    const float* p2w1 = (const float*)d_in[13];
    const float* p2b1 = (const float*)d_in[14];
    const float* p2g1 = (const float*)d_in[15];
    const float* p2be1= (const float*)d_in[16];
    float* out = (float*)d_out;

    k_initpack<<<128, 256>>>(pts);
    k_knn<<<dim3(NN/16, BB), 256>>>();
    k_pass2<<<dim3(NN/128, BB, 2), 320>>>(p1w0, p1b0, p1g0, p1be0, p1w1, p1b1);
    k_tail1<<<dim3(KK, BB), 512>>>(p1g1, p1be1, p2w0, p2b0);
    k_tail2<<<BB*80, 256>>>(p2g0, p2be0, p2w1, p2b1);
    k_fin<<<(BB*1024*KK + 255)/256, 256>>>(p2g1, p2be1, out);
}